// round 2
// baseline (speedup 1.0000x reference)
#include <cuda_runtime.h>
#include <math_constants.h>

#define BN_EPS 1e-3f
#define NPTS 2048
#define NBATCH 8
#define NROWS (NPTS * NBATCH)
#define KNN 16

__device__ float g_xcat[NROWS * 512];
__device__ float g_ytb[NROWS * 512];
__device__ float g_sq[NROWS];
__device__ int   g_idx[NROWS * KNN];

// ---------------------------------------------------------------------------
// squared norms per row (only needed for the raw input x, C=3)
// ---------------------------------------------------------------------------
__global__ void sqnorm_kernel(const float* __restrict__ x, int lda, int C,
                              float* __restrict__ sq) {
    int i = blockIdx.x * blockDim.x + threadIdx.x;
    if (i < NROWS) {
        const float* p = x + (long long)i * lda;
        float s = 0.f;
        for (int c = 0; c < C; c++) { float v = p[c]; s = fmaf(v, v, s); }
        sq[i] = s;
    }
}

// ---------------------------------------------------------------------------
// top-16 insertion (register-resident list; track current min for fast reject)
// ---------------------------------------------------------------------------
__device__ __forceinline__ void topk_ins(float (&v)[16], int (&id)[16],
                                         float& vmin, int& vminid, int& minpos,
                                         float pv, int jg) {
    if (pv > vmin || (pv == vmin && jg < vminid)) {
#pragma unroll
        for (int q = 0; q < 16; q++)
            if (q == minpos) { v[q] = pv; id[q] = jg; }
        vmin = v[0]; vminid = id[0]; minpos = 0;
#pragma unroll
        for (int q = 1; q < 16; q++) {
            bool w = (v[q] < vmin) || (v[q] == vmin && id[q] > vminid);
            if (w) { vmin = v[q]; vminid = id[q]; minpos = q; }
        }
    }
}

// ---------------------------------------------------------------------------
// kNN: 64 i-rows x 128 j-cols per tile, 256 threads, 4x8 micro-tile.
// pd = 2*dot - sq_i - sq_j; top-16 per row, ties -> lower index.
// C chunked by 64 through shared. Selection: 4 threads per row, shuffle merge.
// ---------------------------------------------------------------------------
__global__ void __launch_bounds__(256, 2)
knn_kernel(const float* __restrict__ x, int lda, int C,
           const float* __restrict__ sq, int* __restrict__ outidx) {
    extern __shared__ float sm[];
    float* xiT = sm;                    // C x 68  (xiT[c*68 + i])
    float* xjT = sm + C * 68;           // 64 x 132 (chunk) (xjT[c*132 + j])
    float* pd  = xjT + 64 * 132;        // 64 x 132 (pd[i*132 + j])

    const int rowbase = blockIdx.y * NPTS;
    const int i0 = blockIdx.x * 64;
    const int tid = threadIdx.x;
    const int ty = tid >> 4, tx = tid & 15;     // dot phase: 16x16 thread grid
    const int srow = tid >> 2, sq4 = tid & 3;   // selection: 4 lanes per row

    // load xi tile transposed (held for whole block)
    for (int t = tid; t < 64 * C; t += 256) {
        int i = t / C, c = t - i * C;
        xiT[c * 68 + i] = x[(long long)(rowbase + i0 + i) * lda + c];
    }
    float sqi[4];
#pragma unroll
    for (int r = 0; r < 4; r++) sqi[r] = sq[rowbase + i0 + ty * 4 + r];

    float v[16]; int id[16];
#pragma unroll
    for (int q = 0; q < 16; q++) { v[q] = -CUDART_INF_F; id[q] = 0x7fffffff; }
    float vmin = -CUDART_INF_F; int vminid = 0x7fffffff; int minpos = 0;

    float acc[4][8];
#pragma unroll
    for (int r = 0; r < 4; r++)
#pragma unroll
        for (int j = 0; j < 8; j++) acc[r][j] = 0.f;

    const int NCH = (C + 63) >> 6;

    for (int jt = 0; jt < NPTS / 128; jt++) {
        const int j0 = jt * 128;
        for (int ch = 0; ch < NCH; ch++) {
            const int cb = ch << 6;
            const int CH = (C - cb < 64) ? (C - cb) : 64;
            __syncthreads();   // prev chunk reads / prev selection done
            for (int t = tid; t < 128 * CH; t += 256) {
                int j = t / CH, c = t - j * CH;
                xjT[c * 132 + j] = x[(long long)(rowbase + j0 + j) * lda + cb + c];
            }
            __syncthreads();
            const float* xip = xiT + cb * 68 + ty * 4;
            for (int c = 0; c < CH; c++) {
                float4 ai = *(const float4*)(xip + c * 68);
                float4 b0 = *(const float4*)&xjT[c * 132 + tx * 4];
                float4 b1 = *(const float4*)&xjT[c * 132 + 64 + tx * 4];
                acc[0][0] = fmaf(ai.x, b0.x, acc[0][0]); acc[0][1] = fmaf(ai.x, b0.y, acc[0][1]);
                acc[0][2] = fmaf(ai.x, b0.z, acc[0][2]); acc[0][3] = fmaf(ai.x, b0.w, acc[0][3]);
                acc[0][4] = fmaf(ai.x, b1.x, acc[0][4]); acc[0][5] = fmaf(ai.x, b1.y, acc[0][5]);
                acc[0][6] = fmaf(ai.x, b1.z, acc[0][6]); acc[0][7] = fmaf(ai.x, b1.w, acc[0][7]);
                acc[1][0] = fmaf(ai.y, b0.x, acc[1][0]); acc[1][1] = fmaf(ai.y, b0.y, acc[1][1]);
                acc[1][2] = fmaf(ai.y, b0.z, acc[1][2]); acc[1][3] = fmaf(ai.y, b0.w, acc[1][3]);
                acc[1][4] = fmaf(ai.y, b1.x, acc[1][4]); acc[1][5] = fmaf(ai.y, b1.y, acc[1][5]);
                acc[1][6] = fmaf(ai.y, b1.z, acc[1][6]); acc[1][7] = fmaf(ai.y, b1.w, acc[1][7]);
                acc[2][0] = fmaf(ai.z, b0.x, acc[2][0]); acc[2][1] = fmaf(ai.z, b0.y, acc[2][1]);
                acc[2][2] = fmaf(ai.z, b0.z, acc[2][2]); acc[2][3] = fmaf(ai.z, b0.w, acc[2][3]);
                acc[2][4] = fmaf(ai.z, b1.x, acc[2][4]); acc[2][5] = fmaf(ai.z, b1.y, acc[2][5]);
                acc[2][6] = fmaf(ai.z, b1.z, acc[2][6]); acc[2][7] = fmaf(ai.z, b1.w, acc[2][7]);
                acc[3][0] = fmaf(ai.w, b0.x, acc[3][0]); acc[3][1] = fmaf(ai.w, b0.y, acc[3][1]);
                acc[3][2] = fmaf(ai.w, b0.z, acc[3][2]); acc[3][3] = fmaf(ai.w, b0.w, acc[3][3]);
                acc[3][4] = fmaf(ai.w, b1.x, acc[3][4]); acc[3][5] = fmaf(ai.w, b1.y, acc[3][5]);
                acc[3][6] = fmaf(ai.w, b1.z, acc[3][6]); acc[3][7] = fmaf(ai.w, b1.w, acc[3][7]);
            }
        }
        // epilogue: pd = 2*dot - sqi - sqj, write to shared
        float4 sjA = *(const float4*)&sq[rowbase + j0 + tx * 4];
        float4 sjB = *(const float4*)&sq[rowbase + j0 + 64 + tx * 4];
#pragma unroll
        for (int r = 0; r < 4; r++) {
            float4 o0, o1;
            o0.x = 2.f * acc[r][0] - sqi[r] - sjA.x;
            o0.y = 2.f * acc[r][1] - sqi[r] - sjA.y;
            o0.z = 2.f * acc[r][2] - sqi[r] - sjA.z;
            o0.w = 2.f * acc[r][3] - sqi[r] - sjA.w;
            o1.x = 2.f * acc[r][4] - sqi[r] - sjB.x;
            o1.y = 2.f * acc[r][5] - sqi[r] - sjB.y;
            o1.z = 2.f * acc[r][6] - sqi[r] - sjB.z;
            o1.w = 2.f * acc[r][7] - sqi[r] - sjB.w;
            *(float4*)&pd[(ty * 4 + r) * 132 + tx * 4] = o0;
            *(float4*)&pd[(ty * 4 + r) * 132 + 64 + tx * 4] = o1;
#pragma unroll
            for (int j = 0; j < 8; j++) acc[r][j] = 0.f;
        }
        __syncthreads();
        // selection: thread (srow, sq4) scans j strip [sq4*32, sq4*32+32)
#pragma unroll
        for (int s = 0; s < 8; s++) {
            const float4 pv = *(const float4*)&pd[srow * 132 + sq4 * 32 + s * 4];
            int jb = j0 + sq4 * 32 + s * 4;
            topk_ins(v, id, vmin, vminid, minpos, pv.x, jb);
            topk_ins(v, id, vmin, vminid, minpos, pv.y, jb + 1);
            topk_ins(v, id, vmin, vminid, minpos, pv.z, jb + 2);
            topk_ins(v, id, vmin, vminid, minpos, pv.w, jb + 3);
        }
        // next tile's first __syncthreads() protects pd/xjT reuse
    }

    // merge 4 lanes x 16 entries -> top-16 per row via warp shuffles
    for (int t = 0; t < KNN; t++) {
        float bv = -CUDART_INF_F; int bid = 0x7fffffff; int bq = 0;
#pragma unroll
        for (int q = 0; q < 16; q++) {
            bool w = (v[q] > bv) || (v[q] == bv && id[q] < bid);
            if (w) { bv = v[q]; bid = id[q]; bq = q; }
        }
        float lv = bv; int lid = bid;
#pragma unroll
        for (int off = 1; off < 4; off <<= 1) {
            float ov = __shfl_xor_sync(0xffffffffu, bv, off);
            int oid = __shfl_xor_sync(0xffffffffu, bid, off);
            if (ov > bv || (ov == bv && oid < bid)) { bv = ov; bid = oid; }
        }
        if (lid == bid && lv == bv) { v[bq] = -CUDART_INF_F; id[bq] = 0x7fffffff; }
        if (sq4 == 0) outidx[(long long)(rowbase + i0 + srow) * KNN + t] = bid;
    }
}

// ---------------------------------------------------------------------------
// SGEMM 64x64x16 tiles, 256 threads, 4x4 micro-tile, double-buffered smem.
// dual: output [rows, 2D] = A @ [Wtop | Wbot] where Wtop=W[0:K], Wbot=W[K:2K].
// Optional fused BN+ReLU (final layer).
// ---------------------------------------------------------------------------
__global__ void sgemm_kernel(const float* __restrict__ A, int lda,
                             const float* __restrict__ W, int K, int D, int dual,
                             float* __restrict__ Co, int ldc,
                             const float* __restrict__ bg, const float* __restrict__ bb,
                             const float* __restrict__ bm, const float* __restrict__ bvv) {
    __shared__ float As[2][16 * 68];
    __shared__ float Bs[2][16 * 68];
    const int mb = blockIdx.y * 64, nb = blockIdx.x * 64;
    const int tid = threadIdx.x;
    const int ry = tid >> 4, rx = tid & 15;
    float acc[4][4] = {};
    float ra[4], rb[4];

    const int am = (tid >> 4), ak = (tid & 15);        // A loader: t = tid + u*256 -> m = am + u*16? (recompute below)
    (void)am; (void)ak;

    // --- load tile 0 ---
#pragma unroll
    for (int u = 0; u < 4; u++) {
        int t = tid + u * 256; int m = t >> 4, k = t & 15;
        ra[u] = (k < K) ? A[(long long)(mb + m) * lda + k] : 0.f;
    }
#pragma unroll
    for (int u = 0; u < 4; u++) {
        int t = tid + u * 256; int k = t >> 6, n = t & 63;
        int gn = nb + n;
        float val = 0.f;
        if (k < K) {
            if (!dual) val = W[(long long)k * D + gn];
            else if (gn < D) val = W[(long long)k * D + gn];
            else val = W[(long long)(K + k) * D + gn - D];
        }
        rb[u] = val;
    }
#pragma unroll
    for (int u = 0; u < 4; u++) {
        int t = tid + u * 256;
        As[0][(t & 15) * 68 + (t >> 4)] = ra[u];
        Bs[0][(t >> 6) * 68 + (t & 63)] = rb[u];
    }
    __syncthreads();

    int p = 0;
    for (int kt = 0; kt < K; kt += 16) {
        const bool more = (kt + 16 < K);
        if (more) {
#pragma unroll
            for (int u = 0; u < 4; u++) {
                int t = tid + u * 256; int m = t >> 4, k = kt + 16 + (t & 15);
                ra[u] = (k < K) ? A[(long long)(mb + m) * lda + k] : 0.f;
            }
#pragma unroll
            for (int u = 0; u < 4; u++) {
                int t = tid + u * 256; int k = kt + 16 + (t >> 6), n = t & 63;
                int gn = nb + n;
                float val = 0.f;
                if (k < K) {
                    if (!dual) val = W[(long long)k * D + gn];
                    else if (gn < D) val = W[(long long)k * D + gn];
                    else val = W[(long long)(K + k) * D + gn - D];
                }
                rb[u] = val;
            }
        }
#pragma unroll
        for (int k = 0; k < 16; k++) {
            float4 a = *(const float4*)&As[p][k * 68 + ry * 4];
            float4 bq = *(const float4*)&Bs[p][k * 68 + rx * 4];
            acc[0][0] = fmaf(a.x, bq.x, acc[0][0]); acc[0][1] = fmaf(a.x, bq.y, acc[0][1]);
            acc[0][2] = fmaf(a.x, bq.z, acc[0][2]); acc[0][3] = fmaf(a.x, bq.w, acc[0][3]);
            acc[1][0] = fmaf(a.y, bq.x, acc[1][0]); acc[1][1] = fmaf(a.y, bq.y, acc[1][1]);
            acc[1][2] = fmaf(a.y, bq.z, acc[1][2]); acc[1][3] = fmaf(a.y, bq.w, acc[1][3]);
            acc[2][0] = fmaf(a.z, bq.x, acc[2][0]); acc[2][1] = fmaf(a.z, bq.y, acc[2][1]);
            acc[2][2] = fmaf(a.z, bq.z, acc[2][2]); acc[2][3] = fmaf(a.z, bq.w, acc[2][3]);
            acc[3][0] = fmaf(a.w, bq.x, acc[3][0]); acc[3][1] = fmaf(a.w, bq.y, acc[3][1]);
            acc[3][2] = fmaf(a.w, bq.z, acc[3][2]); acc[3][3] = fmaf(a.w, bq.w, acc[3][3]);
        }
        if (more) {
            __syncthreads();
#pragma unroll
            for (int u = 0; u < 4; u++) {
                int t = tid + u * 256;
                As[p ^ 1][(t & 15) * 68 + (t >> 4)] = ra[u];
                Bs[p ^ 1][(t >> 6) * 68 + (t & 63)] = rb[u];
            }
            __syncthreads();
            p ^= 1;
        }
    }

    if (bg) {
#pragma unroll
        for (int j = 0; j < 4; j++) {
            int n = nb + rx * 4 + j;
            float s = bg[n] * rsqrtf(bvv[n] + BN_EPS);
            float t = bb[n] - bm[n] * s;
#pragma unroll
            for (int i = 0; i < 4; i++) acc[i][j] = fmaxf(fmaf(acc[i][j], s, t), 0.f);
        }
    }
#pragma unroll
    for (int i = 0; i < 4; i++) {
        *(float4*)&Co[(long long)(mb + ry * 4 + i) * ldc + nb + rx * 4] =
            make_float4(acc[i][0], acc[i][1], acc[i][2], acc[i][3]);
    }
}

// ---------------------------------------------------------------------------
// gather + BN + ReLU + max over k=16 neighbors, fused next-stage sqnorm.
// ytb layout per row: [ytop(0..D) | ybot(D..2D)]
// ---------------------------------------------------------------------------
__global__ void gathermax_kernel(const float* __restrict__ ytb, const int* __restrict__ idx,
                                 int D,
                                 const float* __restrict__ g, const float* __restrict__ b,
                                 const float* __restrict__ m, const float* __restrict__ vv,
                                 float* __restrict__ out, float* __restrict__ sqout) {
    const int row = blockIdx.x;
    const int base = row & ~(NPTS - 1);
    __shared__ int sid[KNN];
    __shared__ float wred[2];
    const int tid = threadIdx.x;  // 64
    if (tid < KNN) sid[tid] = idx[(long long)row * KNN + tid];
    __syncthreads();
    const float* top = ytb + (long long)row * 2 * D;
    float ss = 0.f;
    for (int d = tid * 4; d < D; d += 256) {
        float4 g4 = *(const float4*)&g[d];
        float4 v4 = *(const float4*)&vv[d];
        float4 b4 = *(const float4*)&b[d];
        float4 m4 = *(const float4*)&m[d];
        float4 s4, t4;
        s4.x = g4.x * rsqrtf(v4.x + BN_EPS); t4.x = b4.x - m4.x * s4.x;
        s4.y = g4.y * rsqrtf(v4.y + BN_EPS); t4.y = b4.y - m4.y * s4.y;
        s4.z = g4.z * rsqrtf(v4.z + BN_EPS); t4.z = b4.z - m4.z * s4.z;
        s4.w = g4.w * rsqrtf(v4.w + BN_EPS); t4.w = b4.w - m4.w * s4.w;
        float4 tp = *(const float4*)&top[d];
        float4 best = make_float4(-CUDART_INF_F, -CUDART_INF_F, -CUDART_INF_F, -CUDART_INF_F);
#pragma unroll
        for (int k = 0; k < KNN; k++) {
            const float4 yb = *(const float4*)&ytb[(long long)(base + sid[k]) * 2 * D + D + d];
            best.x = fmaxf(best.x, fmaf(tp.x + yb.x, s4.x, t4.x));
            best.y = fmaxf(best.y, fmaf(tp.y + yb.y, s4.y, t4.y));
            best.z = fmaxf(best.z, fmaf(tp.z + yb.z, s4.z, t4.z));
            best.w = fmaxf(best.w, fmaf(tp.w + yb.w, s4.w, t4.w));
        }
        best.x = fmaxf(best.x, 0.f); best.y = fmaxf(best.y, 0.f);
        best.z = fmaxf(best.z, 0.f); best.w = fmaxf(best.w, 0.f);
        *(float4*)&out[(long long)row * 512 + d] = best;
        ss += best.x * best.x + best.y * best.y + best.z * best.z + best.w * best.w;
    }
#pragma unroll
    for (int off = 16; off > 0; off >>= 1) ss += __shfl_down_sync(0xffffffffu, ss, off);
    if ((tid & 31) == 0) wred[tid >> 5] = ss;
    __syncthreads();
    if (tid == 0) sqout[row] = wred[0] + wred[1];
}

// ---------------------------------------------------------------------------
extern "C" void kernel_launch(void* const* d_in, const int* in_sizes, int n_in,
                              void* d_out, int out_size) {
    const float* x = (const float*)d_in[0];
    const float *W[5], *gg[5], *bb[5], *mm[5], *vv[5];
    for (int i = 0; i < 5; i++) {
        W[i]  = (const float*)d_in[1 + 5 * i];
        gg[i] = (const float*)d_in[2 + 5 * i];
        bb[i] = (const float*)d_in[3 + 5 * i];
        mm[i] = (const float*)d_in[4 + 5 * i];
        vv[i] = (const float*)d_in[5 + 5 * i];
    }
    float *xcat, *ytb, *sqp; int* idxp;
    cudaGetSymbolAddress((void**)&xcat, g_xcat);
    cudaGetSymbolAddress((void**)&ytb, g_ytb);
    cudaGetSymbolAddress((void**)&sqp, g_sq);
    cudaGetSymbolAddress((void**)&idxp, g_idx);

    cudaFuncSetAttribute(knn_kernel, cudaFuncAttributeMaxDynamicSharedMemorySize, 102400);

    const int Cs[4] = {3, 64, 64, 128};
    const int Ds[4] = {64, 64, 128, 256};

    sqnorm_kernel<<<NROWS / 256, 256>>>(x, 3, 3, sqp);

    const float* in = x;
    int lda = 3;
    int coloff = 0;
    for (int s = 0; s < 4; s++) {
        const int C = Cs[s], D = Ds[s];
        size_t smem = (size_t)(C * 68 + 2 * 64 * 132) * 4;
        knn_kernel<<<dim3(NPTS / 64, NBATCH), 256, smem>>>(in, lda, C, sqp, idxp);
        sgemm_kernel<<<dim3(2 * D / 64, NROWS / 64), 256>>>(in, lda, W[s], C, D, 1,
                                                            ytb, 2 * D,
                                                            nullptr, nullptr, nullptr, nullptr);
        float* outp = xcat + coloff;
        gathermax_kernel<<<NROWS, 64>>>(ytb, idxp, D, gg[s], bb[s], mm[s], vv[s],
                                        outp, sqp);
        in = outp; lda = 512;
        coloff += D;
    }
    // final: relu(bn(xcat @ W5)) -> d_out
    sgemm_kernel<<<dim3(512 / 64, NROWS / 64), 256>>>(xcat, 512, W[4], 512, 512, 0,
                                                      (float*)d_out, 512,
                                                      gg[4], bb[4], mm[4], vv[4]);
}

// round 3
// speedup vs baseline: 2.8512x; 2.8512x over previous
#include <cuda_runtime.h>
#include <math_constants.h>

#define BN_EPS 1e-3f
#define NPTS 2048
#define NBATCH 8
#define NROWS (NPTS * NBATCH)
#define KNN 16

__device__ float g_xcat[NROWS * 512];
__device__ float g_ytb[NROWS * 512];
__device__ float g_sq[NROWS];
__device__ int   g_idx[NROWS * KNN];

// ---------------------------------------------------------------------------
// squared norms per row (only needed for the raw input x, C=3)
// ---------------------------------------------------------------------------
__global__ void sqnorm_kernel(const float* __restrict__ x, int lda, int C,
                              float* __restrict__ sq) {
    int i = blockIdx.x * blockDim.x + threadIdx.x;
    if (i < NROWS) {
        const float* p = x + (long long)i * lda;
        float s = 0.f;
        for (int c = 0; c < C; c++) { float v = p[c]; s = fmaf(v, v, s); }
        sq[i] = s;
    }
}

// ---------------------------------------------------------------------------
// top-16 insertion (register-resident list; track current min for fast reject)
// ---------------------------------------------------------------------------
__device__ __forceinline__ void topk_ins(float (&v)[16], int (&id)[16],
                                         float& vmin, int& vminid, int& minpos,
                                         float pv, int jg) {
    if (pv > vmin || (pv == vmin && jg < vminid)) {
#pragma unroll
        for (int q = 0; q < 16; q++)
            if (q == minpos) { v[q] = pv; id[q] = jg; }
        vmin = v[0]; vminid = id[0]; minpos = 0;
#pragma unroll
        for (int q = 1; q < 16; q++) {
            bool w = (v[q] < vmin) || (v[q] == vmin && id[q] > vminid);
            if (w) { vmin = v[q]; vminid = id[q]; minpos = q; }
        }
    }
}

// ---------------------------------------------------------------------------
// kNN: 64 i-rows x 64 j-cols per tile, 256 threads, 4x4 micro-tile.
// pd = 2*dot - sq_i - sq_j; top-16 per row, ties -> lower index.
// Full C held in shared (C <= 128). Selection: 4 lanes/row, shuffle merge.
// ---------------------------------------------------------------------------
__global__ void __launch_bounds__(256)
knn_kernel(const float* __restrict__ x, int lda, int C,
           const float* __restrict__ sq, int* __restrict__ outidx) {
    extern __shared__ float sm[];
    float* xiT = sm;                 // C x 68  (xiT[c*68 + i])
    float* xjT = sm + C * 68;        // C x 68  (xjT[c*68 + j])
    float* pd  = xjT + C * 68;       // 64 x 68 (pd[i*68 + j])

    const int rowbase = blockIdx.y * NPTS;
    const int i0 = blockIdx.x * 64;
    const int tid = threadIdx.x;
    const int ty = tid >> 4, tx = tid & 15;     // dot phase: 16x16 thread grid
    const int srow = tid >> 2, sq4 = tid & 3;   // selection: 4 lanes per row

    // load xi tile transposed (held for whole block)
    for (int t = tid; t < 64 * C; t += 256) {
        int i = t / C, c = t - i * C;
        xiT[c * 68 + i] = x[(long long)(rowbase + i0 + i) * lda + c];
    }
    float sqi[4];
#pragma unroll
    for (int r = 0; r < 4; r++) sqi[r] = sq[rowbase + i0 + ty * 4 + r];

    float v[16]; int id[16];
#pragma unroll
    for (int q = 0; q < 16; q++) { v[q] = -CUDART_INF_F; id[q] = 0x7fffffff; }
    float vmin = -CUDART_INF_F; int vminid = 0x7fffffff; int minpos = 0;

    for (int jt = 0; jt < NPTS / 64; jt++) {
        const int j0 = jt * 64;
        __syncthreads();   // prev tile: selection done, xjT consumers done
        for (int t = tid; t < 64 * C; t += 256) {
            int j = t / C, c = t - j * C;
            xjT[c * 68 + j] = x[(long long)(rowbase + j0 + j) * lda + c];
        }
        __syncthreads();

        float acc[4][4];
#pragma unroll
        for (int r = 0; r < 4; r++)
#pragma unroll
            for (int j = 0; j < 4; j++) acc[r][j] = 0.f;

        const float* xip = xiT + ty * 4;
        const float* xjp = xjT + tx * 4;
#pragma unroll 4
        for (int c = 0; c < C; c++) {
            float4 ai = *(const float4*)(xip + c * 68);
            float4 bj = *(const float4*)(xjp + c * 68);
            acc[0][0] = fmaf(ai.x, bj.x, acc[0][0]); acc[0][1] = fmaf(ai.x, bj.y, acc[0][1]);
            acc[0][2] = fmaf(ai.x, bj.z, acc[0][2]); acc[0][3] = fmaf(ai.x, bj.w, acc[0][3]);
            acc[1][0] = fmaf(ai.y, bj.x, acc[1][0]); acc[1][1] = fmaf(ai.y, bj.y, acc[1][1]);
            acc[1][2] = fmaf(ai.y, bj.z, acc[1][2]); acc[1][3] = fmaf(ai.y, bj.w, acc[1][3]);
            acc[2][0] = fmaf(ai.z, bj.x, acc[2][0]); acc[2][1] = fmaf(ai.z, bj.y, acc[2][1]);
            acc[2][2] = fmaf(ai.z, bj.z, acc[2][2]); acc[2][3] = fmaf(ai.z, bj.w, acc[2][3]);
            acc[3][0] = fmaf(ai.w, bj.x, acc[3][0]); acc[3][1] = fmaf(ai.w, bj.y, acc[3][1]);
            acc[3][2] = fmaf(ai.w, bj.z, acc[3][2]); acc[3][3] = fmaf(ai.w, bj.w, acc[3][3]);
        }

        // epilogue: pd = 2*dot - sqi - sqj -> shared
        float4 sj = *(const float4*)&sq[rowbase + j0 + tx * 4];
#pragma unroll
        for (int r = 0; r < 4; r++) {
            float4 o;
            o.x = 2.f * acc[r][0] - sqi[r] - sj.x;
            o.y = 2.f * acc[r][1] - sqi[r] - sj.y;
            o.z = 2.f * acc[r][2] - sqi[r] - sj.z;
            o.w = 2.f * acc[r][3] - sqi[r] - sj.w;
            *(float4*)&pd[(ty * 4 + r) * 68 + tx * 4] = o;
        }
        __syncthreads();

        // selection: thread (srow, sq4) scans j strip [sq4*16, sq4*16+16)
#pragma unroll
        for (int s = 0; s < 4; s++) {
            const float4 pv = *(const float4*)&pd[srow * 68 + sq4 * 16 + s * 4];
            int jb = j0 + sq4 * 16 + s * 4;
            topk_ins(v, id, vmin, vminid, minpos, pv.x, jb);
            topk_ins(v, id, vmin, vminid, minpos, pv.y, jb + 1);
            topk_ins(v, id, vmin, vminid, minpos, pv.z, jb + 2);
            topk_ins(v, id, vmin, vminid, minpos, pv.w, jb + 3);
        }
    }

    // merge 4 lanes x 16 entries -> top-16 per row via warp shuffles
    for (int t = 0; t < KNN; t++) {
        float bv = -CUDART_INF_F; int bid = 0x7fffffff; int bq = 0;
#pragma unroll
        for (int q = 0; q < 16; q++) {
            bool w = (v[q] > bv) || (v[q] == bv && id[q] < bid);
            if (w) { bv = v[q]; bid = id[q]; bq = q; }
        }
        float lv = bv; int lid = bid;
#pragma unroll
        for (int off = 1; off < 4; off <<= 1) {
            float ov = __shfl_xor_sync(0xffffffffu, bv, off);
            int oid = __shfl_xor_sync(0xffffffffu, bid, off);
            if (ov > bv || (ov == bv && oid < bid)) { bv = ov; bid = oid; }
        }
        if (lid == bid && lv == bv) { v[bq] = -CUDART_INF_F; id[bq] = 0x7fffffff; }
        if (sq4 == 0) outidx[(long long)(rowbase + i0 + srow) * KNN + t] = bid;
    }
}

// ---------------------------------------------------------------------------
// SGEMM 64x64x16 tiles, 256 threads, 4x4 micro-tile, double-buffered smem.
// dual: output [rows, 2D] = A @ [Wtop | Wbot] (Wtop=W[0:K], Wbot=W[K:2K]).
// Optional fused BN+ReLU (final layer).
// ---------------------------------------------------------------------------
__global__ void sgemm_kernel(const float* __restrict__ A, int lda,
                             const float* __restrict__ W, int K, int D, int dual,
                             float* __restrict__ Co, int ldc,
                             const float* __restrict__ bg, const float* __restrict__ bb,
                             const float* __restrict__ bm, const float* __restrict__ bvv) {
    __shared__ float As[2][16 * 68];
    __shared__ float Bs[2][16 * 68];
    const int mb = blockIdx.y * 64, nb = blockIdx.x * 64;
    const int tid = threadIdx.x;
    const int ry = tid >> 4, rx = tid & 15;
    float acc[4][4] = {};
    float ra[4], rb[4];

#pragma unroll
    for (int u = 0; u < 4; u++) {
        int t = tid + u * 256; int m = t >> 4, k = t & 15;
        ra[u] = (k < K) ? A[(long long)(mb + m) * lda + k] : 0.f;
    }
#pragma unroll
    for (int u = 0; u < 4; u++) {
        int t = tid + u * 256; int k = t >> 6, n = t & 63;
        int gn = nb + n;
        float val = 0.f;
        if (k < K) {
            if (!dual) val = W[(long long)k * D + gn];
            else if (gn < D) val = W[(long long)k * D + gn];
            else val = W[(long long)(K + k) * D + gn - D];
        }
        rb[u] = val;
    }
#pragma unroll
    for (int u = 0; u < 4; u++) {
        int t = tid + u * 256;
        As[0][(t & 15) * 68 + (t >> 4)] = ra[u];
        Bs[0][(t >> 6) * 68 + (t & 63)] = rb[u];
    }
    __syncthreads();

    int p = 0;
    for (int kt = 0; kt < K; kt += 16) {
        const bool more = (kt + 16 < K);
        if (more) {
#pragma unroll
            for (int u = 0; u < 4; u++) {
                int t = tid + u * 256; int m = t >> 4, k = kt + 16 + (t & 15);
                ra[u] = (k < K) ? A[(long long)(mb + m) * lda + k] : 0.f;
            }
#pragma unroll
            for (int u = 0; u < 4; u++) {
                int t = tid + u * 256; int k = kt + 16 + (t >> 6), n = t & 63;
                int gn = nb + n;
                float val = 0.f;
                if (k < K) {
                    if (!dual) val = W[(long long)k * D + gn];
                    else if (gn < D) val = W[(long long)k * D + gn];
                    else val = W[(long long)(K + k) * D + gn - D];
                }
                rb[u] = val;
            }
        }
#pragma unroll
        for (int k = 0; k < 16; k++) {
            float4 a = *(const float4*)&As[p][k * 68 + ry * 4];
            float4 bq = *(const float4*)&Bs[p][k * 68 + rx * 4];
            acc[0][0] = fmaf(a.x, bq.x, acc[0][0]); acc[0][1] = fmaf(a.x, bq.y, acc[0][1]);
            acc[0][2] = fmaf(a.x, bq.z, acc[0][2]); acc[0][3] = fmaf(a.x, bq.w, acc[0][3]);
            acc[1][0] = fmaf(a.y, bq.x, acc[1][0]); acc[1][1] = fmaf(a.y, bq.y, acc[1][1]);
            acc[1][2] = fmaf(a.y, bq.z, acc[1][2]); acc[1][3] = fmaf(a.y, bq.w, acc[1][3]);
            acc[2][0] = fmaf(a.z, bq.x, acc[2][0]); acc[2][1] = fmaf(a.z, bq.y, acc[2][1]);
            acc[2][2] = fmaf(a.z, bq.z, acc[2][2]); acc[2][3] = fmaf(a.z, bq.w, acc[2][3]);
            acc[3][0] = fmaf(a.w, bq.x, acc[3][0]); acc[3][1] = fmaf(a.w, bq.y, acc[3][1]);
            acc[3][2] = fmaf(a.w, bq.z, acc[3][2]); acc[3][3] = fmaf(a.w, bq.w, acc[3][3]);
        }
        if (more) {
            __syncthreads();
#pragma unroll
            for (int u = 0; u < 4; u++) {
                int t = tid + u * 256;
                As[p ^ 1][(t & 15) * 68 + (t >> 4)] = ra[u];
                Bs[p ^ 1][(t >> 6) * 68 + (t & 63)] = rb[u];
            }
            __syncthreads();
            p ^= 1;
        }
    }

    if (bg) {
#pragma unroll
        for (int j = 0; j < 4; j++) {
            int n = nb + rx * 4 + j;
            float s = bg[n] * rsqrtf(bvv[n] + BN_EPS);
            float t = bb[n] - bm[n] * s;
#pragma unroll
            for (int i = 0; i < 4; i++) acc[i][j] = fmaxf(fmaf(acc[i][j], s, t), 0.f);
        }
    }
#pragma unroll
    for (int i = 0; i < 4; i++) {
        *(float4*)&Co[(long long)(mb + ry * 4 + i) * ldc + nb + rx * 4] =
            make_float4(acc[i][0], acc[i][1], acc[i][2], acc[i][3]);
    }
}

// ---------------------------------------------------------------------------
// gather + BN + ReLU + max over k=16 neighbors; fused next-stage sqnorm.
// One warp per row. ytb row layout: [ytop(0..D) | ybot(D..2D)].
// ---------------------------------------------------------------------------
__global__ void gathermax_kernel(const float* __restrict__ ytb, const int* __restrict__ idx,
                                 int D,
                                 const float* __restrict__ g, const float* __restrict__ b,
                                 const float* __restrict__ m, const float* __restrict__ vv,
                                 float* __restrict__ out, float* __restrict__ sqout) {
    const int warp = (blockIdx.x * blockDim.x + threadIdx.x) >> 5;
    const int lane = threadIdx.x & 31;
    if (warp >= NROWS) return;
    const int row = warp;
    const int base = row & ~(NPTS - 1);
    const int myid = idx[(long long)row * KNN + (lane & 15)];
    const float* top = ytb + (long long)row * 2 * D;
    float ss = 0.f;
    for (int c0 = 0; c0 < D; c0 += 64) {
        const int d = c0 + lane * 2;
        float2 g2 = *(const float2*)&g[d];
        float2 v2 = *(const float2*)&vv[d];
        float2 b2 = *(const float2*)&b[d];
        float2 m2 = *(const float2*)&m[d];
        float sx = g2.x * rsqrtf(v2.x + BN_EPS), txx = b2.x - m2.x * sx;
        float sy = g2.y * rsqrtf(v2.y + BN_EPS), tyy = b2.y - m2.y * sy;
        float2 tp = *(const float2*)&top[d];
        float bx = -CUDART_INF_F, by = -CUDART_INF_F;
#pragma unroll
        for (int k = 0; k < KNN; k++) {
            int sk = __shfl_sync(0xffffffffu, myid, k, 16);
            float2 yb = *(const float2*)&ytb[(long long)(base + sk) * 2 * D + D + d];
            bx = fmaxf(bx, fmaf(tp.x + yb.x, sx, txx));
            by = fmaxf(by, fmaf(tp.y + yb.y, sy, tyy));
        }
        bx = fmaxf(bx, 0.f); by = fmaxf(by, 0.f);
        *(float2*)&out[(long long)row * 512 + d] = make_float2(bx, by);
        ss += bx * bx + by * by;
    }
#pragma unroll
    for (int off = 16; off > 0; off >>= 1) ss += __shfl_down_sync(0xffffffffu, ss, off);
    if (lane == 0) sqout[row] = ss;
}

// ---------------------------------------------------------------------------
extern "C" void kernel_launch(void* const* d_in, const int* in_sizes, int n_in,
                              void* d_out, int out_size) {
    const float* x = (const float*)d_in[0];
    const float *W[5], *gg[5], *bb[5], *mm[5], *vv[5];
    for (int i = 0; i < 5; i++) {
        W[i]  = (const float*)d_in[1 + 5 * i];
        gg[i] = (const float*)d_in[2 + 5 * i];
        bb[i] = (const float*)d_in[3 + 5 * i];
        mm[i] = (const float*)d_in[4 + 5 * i];
        vv[i] = (const float*)d_in[5 + 5 * i];
    }
    float *xcat, *ytb, *sqp; int* idxp;
    cudaGetSymbolAddress((void**)&xcat, g_xcat);
    cudaGetSymbolAddress((void**)&ytb, g_ytb);
    cudaGetSymbolAddress((void**)&sqp, g_sq);
    cudaGetSymbolAddress((void**)&idxp, g_idx);

    cudaFuncSetAttribute(knn_kernel, cudaFuncAttributeMaxDynamicSharedMemorySize, 92160);

    const int Cs[4] = {3, 64, 64, 128};
    const int Ds[4] = {64, 64, 128, 256};

    sqnorm_kernel<<<NROWS / 256, 256>>>(x, 3, 3, sqp);

    const float* in = x;
    int lda = 3;
    int coloff = 0;
    for (int s = 0; s < 4; s++) {
        const int C = Cs[s], D = Ds[s];
        size_t smem = (size_t)(2 * C * 68 + 64 * 68) * 4;
        knn_kernel<<<dim3(NPTS / 64, NBATCH), 256, smem>>>(in, lda, C, sqp, idxp);
        sgemm_kernel<<<dim3(2 * D / 64, NROWS / 64), 256>>>(in, lda, W[s], C, D, 1,
                                                            ytb, 2 * D,
                                                            nullptr, nullptr, nullptr, nullptr);
        float* outp = xcat + coloff;
        gathermax_kernel<<<NROWS / 8, 256>>>(ytb, idxp, D, gg[s], bb[s], mm[s], vv[s],
                                             outp, sqp);
        in = outp; lda = 512;
        coloff += D;
    }
    // final: relu(bn(xcat @ W5)) -> d_out
    sgemm_kernel<<<dim3(512 / 64, NROWS / 64), 256>>>(xcat, 512, W[4], 512, 512, 0,
                                                      (float*)d_out, 512,
                                                      gg[4], bb[4], mm[4], vv[4]);
}

// round 4
// speedup vs baseline: 3.9096x; 1.3712x over previous
#include <cuda_runtime.h>
#include <math_constants.h>

#define BN_EPS 1e-3f
#define NPTS 2048
#define NBATCH 8
#define NROWS (NPTS * NBATCH)
#define KNN 16

typedef unsigned long long u64;

__device__ float g_xcat[NROWS * 512];
__device__ float g_ytb[NROWS * 512];
__device__ float g_sq[NROWS];
__device__ int   g_idx[NROWS * KNN];

// ---------------- f32x2 packed helpers (FFMA2: 2x fp32 throughput) ----------
__device__ __forceinline__ void ffma2(u64& d, u64 a, u64 b) {
    asm("fma.rn.f32x2 %0, %1, %2, %0;" : "+l"(d) : "l"(a), "l"(b));
}
__device__ __forceinline__ float2 unpack2(u64 v) {
    float2 r;
    asm("mov.b64 {%0, %1}, %2;" : "=f"(r.x), "=f"(r.y) : "l"(v));
    return r;
}

// ---------------------------------------------------------------------------
// squared norms per row (raw input only, C=3)
// ---------------------------------------------------------------------------
__global__ void sqnorm_kernel(const float* __restrict__ x, int lda, int C,
                              float* __restrict__ sq) {
    int i = blockIdx.x * blockDim.x + threadIdx.x;
    if (i < NROWS) {
        const float* p = x + (long long)i * lda;
        float s = 0.f;
        for (int c = 0; c < C; c++) { float v = p[c]; s = fmaf(v, v, s); }
        sq[i] = s;
    }
}

// ---------------------------------------------------------------------------
// top-16 insertion (register-resident; fast reject on current min)
// ---------------------------------------------------------------------------
__device__ __forceinline__ void topk_ins(float (&v)[16], int (&id)[16],
                                         float& vmin, int& vminid, int& minpos,
                                         float pv, int jg) {
    if (pv > vmin || (pv == vmin && jg < vminid)) {
#pragma unroll
        for (int q = 0; q < 16; q++)
            if (q == minpos) { v[q] = pv; id[q] = jg; }
        vmin = v[0]; vminid = id[0]; minpos = 0;
#pragma unroll
        for (int q = 1; q < 16; q++) {
            bool w = (v[q] < vmin) || (v[q] == vmin && id[q] > vminid);
            if (w) { vmin = v[q]; vminid = id[q]; minpos = q; }
        }
    }
}

// ---------------------------------------------------------------------------
// kNN: 64 i x 64 j tiles, 256 threads, 4x4 micro-tile in f32x2 (FFMA2).
// xiD holds xi duplicated ((v,v) pairs) so dup operands come from LDS.128.
// pd = 2*dot - sq_i - sq_j; top-16 per row, ties -> lower index.
// ---------------------------------------------------------------------------
template <int C>
__global__ void __launch_bounds__(256)
knn_kernel(const float* __restrict__ x, int lda,
           const float* __restrict__ sq, int* __restrict__ outidx) {
    extern __shared__ float sm[];
    float* xiD = sm;                  // C x 136: xiD[c*136+2i] = xiD[..+2i+1] = xi
    float* xjT = sm + C * 136;        // C x 68:  xjT[c*68 + j]
    float* pd  = xjT + C * 68;        // 64 x 68

    const int rowbase = blockIdx.y * NPTS;
    const int i0 = blockIdx.x * 64;
    const int tid = threadIdx.x;
    const int ty = tid >> 4, tx = tid & 15;
    const int srow = tid >> 2, sq4 = tid & 3;

    for (int t = tid; t < 64 * C; t += 256) {
        int i = t / C, c = t - i * C;
        float val = x[(long long)(rowbase + i0 + i) * lda + c];
        xiD[c * 136 + 2 * i] = val;
        xiD[c * 136 + 2 * i + 1] = val;
    }
    float sqi[4];
#pragma unroll
    for (int r = 0; r < 4; r++) sqi[r] = sq[rowbase + i0 + ty * 4 + r];

    float v[16]; int id[16];
#pragma unroll
    for (int q = 0; q < 16; q++) { v[q] = -CUDART_INF_F; id[q] = 0x7fffffff; }
    float vmin = -CUDART_INF_F; int vminid = 0x7fffffff; int minpos = 0;

    const float* xip = xiD + ty * 8;
    const float* xjp = xjT + tx * 4;

    for (int jt = 0; jt < NPTS / 64; jt++) {
        const int j0 = jt * 64;
        __syncthreads();   // prev tile: selection + xjT consumers done
        for (int t = tid; t < 64 * C; t += 256) {
            int j = t / C, c = t - j * C;
            xjT[c * 68 + j] = x[(long long)(rowbase + j0 + j) * lda + c];
        }
        __syncthreads();

        u64 acc[4][2];
#pragma unroll
        for (int r = 0; r < 4; r++) { acc[r][0] = 0ull; acc[r][1] = 0ull; }

#pragma unroll 4
        for (int c = 0; c < C; c++) {
            ulonglong2 a01 = *(const ulonglong2*)(xip + c * 136);
            ulonglong2 a23 = *(const ulonglong2*)(xip + c * 136 + 4);
            ulonglong2 bj  = *(const ulonglong2*)(xjp + c * 68);
            ffma2(acc[0][0], a01.x, bj.x); ffma2(acc[0][1], a01.x, bj.y);
            ffma2(acc[1][0], a01.y, bj.x); ffma2(acc[1][1], a01.y, bj.y);
            ffma2(acc[2][0], a23.x, bj.x); ffma2(acc[2][1], a23.x, bj.y);
            ffma2(acc[3][0], a23.y, bj.x); ffma2(acc[3][1], a23.y, bj.y);
        }

        float4 sj = *(const float4*)&sq[rowbase + j0 + tx * 4];
#pragma unroll
        for (int r = 0; r < 4; r++) {
            float2 d01 = unpack2(acc[r][0]);
            float2 d23 = unpack2(acc[r][1]);
            float4 o;
            o.x = 2.f * d01.x - sqi[r] - sj.x;
            o.y = 2.f * d01.y - sqi[r] - sj.y;
            o.z = 2.f * d23.x - sqi[r] - sj.z;
            o.w = 2.f * d23.y - sqi[r] - sj.w;
            *(float4*)&pd[(ty * 4 + r) * 68 + tx * 4] = o;
        }
        __syncthreads();

#pragma unroll
        for (int s = 0; s < 4; s++) {
            const float4 pv = *(const float4*)&pd[srow * 68 + sq4 * 16 + s * 4];
            int jb = j0 + sq4 * 16 + s * 4;
            topk_ins(v, id, vmin, vminid, minpos, pv.x, jb);
            topk_ins(v, id, vmin, vminid, minpos, pv.y, jb + 1);
            topk_ins(v, id, vmin, vminid, minpos, pv.z, jb + 2);
            topk_ins(v, id, vmin, vminid, minpos, pv.w, jb + 3);
        }
    }

    // merge 4 lanes x 16 entries -> top-16 per row via warp shuffles
    for (int t = 0; t < KNN; t++) {
        float bv = -CUDART_INF_F; int bid = 0x7fffffff; int bq = 0;
#pragma unroll
        for (int q = 0; q < 16; q++) {
            bool w = (v[q] > bv) || (v[q] == bv && id[q] < bid);
            if (w) { bv = v[q]; bid = id[q]; bq = q; }
        }
        float lv = bv; int lid = bid;
#pragma unroll
        for (int off = 1; off < 4; off <<= 1) {
            float ov = __shfl_xor_sync(0xffffffffu, bv, off);
            int oid = __shfl_xor_sync(0xffffffffu, bid, off);
            if (ov > bv || (ov == bv && oid < bid)) { bv = ov; bid = oid; }
        }
        if (lid == bid && lv == bv) { v[bq] = -CUDART_INF_F; id[bq] = 0x7fffffff; }
        if (sq4 == 0) outidx[(long long)(rowbase + i0 + srow) * KNN + t] = bid;
    }
}

// ---------------------------------------------------------------------------
// SGEMM 64x64x16, 256 threads, 4x4 micro-tile in f32x2, double-buffered.
// As stored duplicated (16 x 136) so a-dup pairs load as LDS.128.
// dual: out [rows,2D] = A @ [Wtop|Wbot]. Optional fused BN+ReLU.
// ---------------------------------------------------------------------------
__global__ void sgemm_kernel(const float* __restrict__ A, int lda,
                             const float* __restrict__ W, int K, int D, int dual,
                             float* __restrict__ Co, int ldc,
                             const float* __restrict__ bg, const float* __restrict__ bb,
                             const float* __restrict__ bm, const float* __restrict__ bvv) {
    __shared__ float As[2][16 * 136];
    __shared__ float Bs[2][16 * 68];
    const int mb = blockIdx.y * 64, nb = blockIdx.x * 64;
    const int tid = threadIdx.x;
    const int ry = tid >> 4, rx = tid & 15;
    u64 acc[4][2];
#pragma unroll
    for (int r = 0; r < 4; r++) { acc[r][0] = 0ull; acc[r][1] = 0ull; }
    float ra[4], rb[4];

#pragma unroll
    for (int u = 0; u < 4; u++) {
        int t = tid + u * 256; int m = t >> 4, k = t & 15;
        ra[u] = (k < K) ? A[(long long)(mb + m) * lda + k] : 0.f;
    }
#pragma unroll
    for (int u = 0; u < 4; u++) {
        int t = tid + u * 256; int k = t >> 6, n = t & 63;
        int gn = nb + n;
        float val = 0.f;
        if (k < K) {
            if (!dual) val = W[(long long)k * D + gn];
            else if (gn < D) val = W[(long long)k * D + gn];
            else val = W[(long long)(K + k) * D + gn - D];
        }
        rb[u] = val;
    }
#pragma unroll
    for (int u = 0; u < 4; u++) {
        int t = tid + u * 256;
        As[0][(t & 15) * 136 + 2 * (t >> 4)] = ra[u];
        As[0][(t & 15) * 136 + 2 * (t >> 4) + 1] = ra[u];
        Bs[0][(t >> 6) * 68 + (t & 63)] = rb[u];
    }
    __syncthreads();

    int p = 0;
    for (int kt = 0; kt < K; kt += 16) {
        const bool more = (kt + 16 < K);
        if (more) {
#pragma unroll
            for (int u = 0; u < 4; u++) {
                int t = tid + u * 256; int m = t >> 4, k = kt + 16 + (t & 15);
                ra[u] = (k < K) ? A[(long long)(mb + m) * lda + k] : 0.f;
            }
#pragma unroll
            for (int u = 0; u < 4; u++) {
                int t = tid + u * 256; int k = kt + 16 + (t >> 6), n = t & 63;
                int gn = nb + n;
                float val = 0.f;
                if (k < K) {
                    if (!dual) val = W[(long long)k * D + gn];
                    else if (gn < D) val = W[(long long)k * D + gn];
                    else val = W[(long long)(K + k) * D + gn - D];
                }
                rb[u] = val;
            }
        }
#pragma unroll
        for (int k = 0; k < 16; k++) {
            ulonglong2 a01 = *(const ulonglong2*)&As[p][k * 136 + ry * 8];
            ulonglong2 a23 = *(const ulonglong2*)&As[p][k * 136 + ry * 8 + 4];
            ulonglong2 bq  = *(const ulonglong2*)&Bs[p][k * 68 + rx * 4];
            ffma2(acc[0][0], a01.x, bq.x); ffma2(acc[0][1], a01.x, bq.y);
            ffma2(acc[1][0], a01.y, bq.x); ffma2(acc[1][1], a01.y, bq.y);
            ffma2(acc[2][0], a23.x, bq.x); ffma2(acc[2][1], a23.x, bq.y);
            ffma2(acc[3][0], a23.y, bq.x); ffma2(acc[3][1], a23.y, bq.y);
        }
        if (more) {
            __syncthreads();
#pragma unroll
            for (int u = 0; u < 4; u++) {
                int t = tid + u * 256;
                As[p ^ 1][(t & 15) * 136 + 2 * (t >> 4)] = ra[u];
                As[p ^ 1][(t & 15) * 136 + 2 * (t >> 4) + 1] = ra[u];
                Bs[p ^ 1][(t >> 6) * 68 + (t & 63)] = rb[u];
            }
            __syncthreads();
            p ^= 1;
        }
    }

    float out[4][4];
#pragma unroll
    for (int i = 0; i < 4; i++) {
        float2 lo = unpack2(acc[i][0]);
        float2 hi = unpack2(acc[i][1]);
        out[i][0] = lo.x; out[i][1] = lo.y; out[i][2] = hi.x; out[i][3] = hi.y;
    }
    if (bg) {
#pragma unroll
        for (int j = 0; j < 4; j++) {
            int n = nb + rx * 4 + j;
            float s = bg[n] * rsqrtf(bvv[n] + BN_EPS);
            float t = bb[n] - bm[n] * s;
#pragma unroll
            for (int i = 0; i < 4; i++) out[i][j] = fmaxf(fmaf(out[i][j], s, t), 0.f);
        }
    }
#pragma unroll
    for (int i = 0; i < 4; i++) {
        *(float4*)&Co[(long long)(mb + ry * 4 + i) * ldc + nb + rx * 4] =
            make_float4(out[i][0], out[i][1], out[i][2], out[i][3]);
    }
}

// ---------------------------------------------------------------------------
// gather + BN + ReLU + max over k=16; fused next-stage sqnorm. Warp per row.
// ---------------------------------------------------------------------------
__global__ void gathermax_kernel(const float* __restrict__ ytb, const int* __restrict__ idx,
                                 int D,
                                 const float* __restrict__ g, const float* __restrict__ b,
                                 const float* __restrict__ m, const float* __restrict__ vv,
                                 float* __restrict__ out, float* __restrict__ sqout) {
    const int warp = (blockIdx.x * blockDim.x + threadIdx.x) >> 5;
    const int lane = threadIdx.x & 31;
    if (warp >= NROWS) return;
    const int row = warp;
    const int base = row & ~(NPTS - 1);
    const int myid = idx[(long long)row * KNN + (lane & 15)];
    const float* top = ytb + (long long)row * 2 * D;
    float ss = 0.f;
    for (int c0 = 0; c0 < D; c0 += 64) {
        const int d = c0 + lane * 2;
        float2 g2 = *(const float2*)&g[d];
        float2 v2 = *(const float2*)&vv[d];
        float2 b2 = *(const float2*)&b[d];
        float2 m2 = *(const float2*)&m[d];
        float sx = g2.x * rsqrtf(v2.x + BN_EPS), txx = b2.x - m2.x * sx;
        float sy = g2.y * rsqrtf(v2.y + BN_EPS), tyy = b2.y - m2.y * sy;
        float2 tp = *(const float2*)&top[d];
        float bx = -CUDART_INF_F, by = -CUDART_INF_F;
#pragma unroll
        for (int k = 0; k < KNN; k++) {
            int sk = __shfl_sync(0xffffffffu, myid, k, 16);
            float2 yb = *(const float2*)&ytb[(long long)(base + sk) * 2 * D + D + d];
            bx = fmaxf(bx, fmaf(tp.x + yb.x, sx, txx));
            by = fmaxf(by, fmaf(tp.y + yb.y, sy, tyy));
        }
        bx = fmaxf(bx, 0.f); by = fmaxf(by, 0.f);
        *(float2*)&out[(long long)row * 512 + d] = make_float2(bx, by);
        ss += bx * bx + by * by;
    }
#pragma unroll
    for (int off = 16; off > 0; off >>= 1) ss += __shfl_down_sync(0xffffffffu, ss, off);
    if (lane == 0) sqout[row] = ss;
}

// ---------------------------------------------------------------------------
template <int C>
static void launch_knn(const float* in, int lda, const float* sqp, int* idxp) {
    size_t smem = (size_t)(C * 136 + C * 68 + 64 * 68) * 4;
    static bool done = false;
    if (!done) {
        cudaFuncSetAttribute(knn_kernel<C>, cudaFuncAttributeMaxDynamicSharedMemorySize,
                             (int)smem);
        done = true;
    }
    knn_kernel<C><<<dim3(NPTS / 64, NBATCH), 256, smem>>>(in, lda, sqp, idxp);
}

extern "C" void kernel_launch(void* const* d_in, const int* in_sizes, int n_in,
                              void* d_out, int out_size) {
    const float* x = (const float*)d_in[0];
    const float *W[5], *gg[5], *bb[5], *mm[5], *vv[5];
    for (int i = 0; i < 5; i++) {
        W[i]  = (const float*)d_in[1 + 5 * i];
        gg[i] = (const float*)d_in[2 + 5 * i];
        bb[i] = (const float*)d_in[3 + 5 * i];
        mm[i] = (const float*)d_in[4 + 5 * i];
        vv[i] = (const float*)d_in[5 + 5 * i];
    }
    float *xcat, *ytb, *sqp; int* idxp;
    cudaGetSymbolAddress((void**)&xcat, g_xcat);
    cudaGetSymbolAddress((void**)&ytb, g_ytb);
    cudaGetSymbolAddress((void**)&sqp, g_sq);
    cudaGetSymbolAddress((void**)&idxp, g_idx);

    const int Cs[4] = {3, 64, 64, 128};
    const int Ds[4] = {64, 64, 128, 256};

    sqnorm_kernel<<<NROWS / 256, 256>>>(x, 3, 3, sqp);

    const float* in = x;
    int lda = 3;
    int coloff = 0;
    for (int s = 0; s < 4; s++) {
        const int C = Cs[s], D = Ds[s];
        if (C == 3)        launch_knn<3>(in, lda, sqp, idxp);
        else if (C == 64)  launch_knn<64>(in, lda, sqp, idxp);
        else               launch_knn<128>(in, lda, sqp, idxp);
        sgemm_kernel<<<dim3(2 * D / 64, NROWS / 64), 256>>>(in, lda, W[s], C, D, 1,
                                                            ytb, 2 * D,
                                                            nullptr, nullptr, nullptr, nullptr);
        float* outp = xcat + coloff;
        gathermax_kernel<<<NROWS / 8, 256>>>(ytb, idxp, D, gg[s], bb[s], mm[s], vv[s],
                                             outp, sqp);
        in = outp; lda = 512;
        coloff += D;
    }
    sgemm_kernel<<<dim3(512 / 64, NROWS / 64), 256>>>(xcat, 512, W[4], 512, 512, 0,
                                                      (float*)d_out, 512,
                                                      gg[4], bb[4], mm[4], vv[4]);
}